// round 15
// baseline (speedup 1.0000x reference)
#include <cuda_runtime.h>
#include <math.h>

#define TT 1024
#define BB 512
#define KK 128

__device__ float g_path[BB];   // gold-path score per batch (path writes, fwd reads)

// ---- gold-path score: one block per batch. Runs FIRST; block 0 zeroes out. ----
__global__ void __launch_bounds__(128) path_kernel(
    const float* __restrict__ em, const int* __restrict__ tags,
    const float* __restrict__ mask, const float* __restrict__ startT,
    const float* __restrict__ trans, const float* __restrict__ endT,
    float* __restrict__ out)
{
    __shared__ float sacc[4], smsum[4];
    const int b = blockIdx.x, tid = threadIdx.x, warp = tid >> 5, lane = tid & 31;
    if (b == 0 && tid == 0) out[0] = 0.0f;   // safe: only fwd (later kernel) writes out
    float acc = 0.0f, msum = 0.0f;
    for (int t = tid; t < TT; t += 128) {
        int   tg = tags[t * BB + b];
        float m  = mask[t * BB + b];
        acc  += em[(t * BB + b) * KK + tg] * m;
        msum += m;
        if (t > 0) {
            int tp = tags[(t - 1) * BB + b];
            acc += trans[tp * KK + tg] * m;
        }
    }
    for (int o = 16; o; o >>= 1) {
        acc  += __shfl_xor_sync(0xffffffffu, acc, o);
        msum += __shfl_xor_sync(0xffffffffu, msum, o);
    }
    if (lane == 0) { sacc[warp] = acc; smsum[warp] = msum; }
    __syncthreads();
    if (tid == 0) {
        float a  = sacc[0] + sacc[1] + sacc[2] + sacc[3];
        float ms = smsum[0] + smsum[1] + smsum[2] + smsum[3];
        int cnt = (int)(ms + 0.5f); if (cnt < 1) cnt = 1;
        a += startT[tags[b]] + endT[tags[(cnt - 1) * BB + b]];
        g_path[b] = a;
    }
}

// ---- forward recurrence: warp-autonomous, int8 DP4A residual matvec ----
// One warp = one batch; lane owns columns j0..j0+3. NO __syncthreads in the loop.
// grid = 128 CTAs x 128 threads = 512 warps (one per SMSP).
__global__ void __launch_bounds__(128) crf_fwd_kernel(
    const float* __restrict__ em,      // [T,B,K]
    const float* __restrict__ mask,    // [T,B]
    const float* __restrict__ startT,  // [K]
    const float* __restrict__ trans,   // [K,K]
    const float* __restrict__ endT,    // [K]
    float* __restrict__ out)
{
    __shared__ int squ[4][2][32];   // [warp][buf][lane] packed int8 state (4 per word)

    const int tid  = threadIdx.x;
    const int lane = tid & 31;
    const int wid  = tid >> 5;
    const int b    = blockIdx.x * 4 + wid;   // batch owned by this warp
    const int j0   = lane * 4;               // first of 4 owned columns

    // ---- global |R| max (warp covers all 128 columns x all rows) ----
    float rl = 0.0f;
    for (int i = 0; i < KK; i++) {
        const float4 tr = *(const float4*)&trans[i * KK + j0];
        rl = fmaxf(rl, fabsf(__expf(tr.x) - 1.0f));
        rl = fmaxf(rl, fabsf(__expf(tr.y) - 1.0f));
        rl = fmaxf(rl, fabsf(__expf(tr.z) - 1.0f));
        rl = fmaxf(rl, fabsf(__expf(tr.w) - 1.0f));
    }
    float rmax = __uint_as_float(__reduce_max_sync(0xffffffffu, __float_as_uint(rl)));
    rmax = fmaxf(rmax, 1e-20f);
    const float sR    = rmax * (1.0f / 127.0f);
    const float invSR = 127.0f / rmax;
    const float onePr = 1.0f + rmax;

    // quantized residual columns: rq[jj][m] packs R[4m..4m+3][j0+jj]
    int rq[4][32];
#pragma unroll 4
    for (int m = 0; m < 32; m++) {
        int w4[4] = {0, 0, 0, 0};
#pragma unroll
        for (int k = 0; k < 4; k++) {
            const float4 tr = *(const float4*)&trans[(4 * m + k) * KK + j0];
            int q0 = __float2int_rn((__expf(tr.x) - 1.0f) * invSR);
            int q1 = __float2int_rn((__expf(tr.y) - 1.0f) * invSR);
            int q2 = __float2int_rn((__expf(tr.z) - 1.0f) * invSR);
            int q3 = __float2int_rn((__expf(tr.w) - 1.0f) * invSR);
            w4[0] |= (q0 & 255) << (8 * k);
            w4[1] |= (q1 & 255) << (8 * k);
            w4[2] |= (q2 & 255) << (8 * k);
            w4[3] |= (q3 & 255) << (8 * k);
        }
        rq[0][m] = w4[0]; rq[1][m] = w4[1]; rq[2][m] = w4[2]; rq[3][m] = w4[3];
    }

    // ---- init state u(0) = exp(start + em0) ----
    float u[4];
    int   Ce = 0;
    {
        const float4 e0 = *(const float4*)&em[b * KK + j0];
        const float4 s0 = *(const float4*)&startT[j0];
        u[0] = __expf(s0.x + e0.x);
        u[1] = __expf(s0.y + e0.y);
        u[2] = __expf(s0.z + e0.z);
        u[3] = __expf(s0.w + e0.w);
    }

    // initial publish into buffer 1 (true-max slow path, one time)
    float sU, Bsum;
    {
        float wm = fmaxf(fmaxf(u[0], u[1]), fmaxf(u[2], u[3]));
        wm = __uint_as_float(__reduce_max_sync(0xffffffffu, __float_as_uint(wm)));
        wm = fmaxf(wm, 1e-30f);
        const float inv = __fdividef(127.0f, wm);
        int q0 = min(__float2int_rn(u[0] * inv), 127);
        int q1 = min(__float2int_rn(u[1] * inv), 127);
        int q2 = min(__float2int_rn(u[2] * inv), 127);
        int q3 = min(__float2int_rn(u[3] * inv), 127);
        squ[wid][1][lane] = (q0 & 255) | ((q1 & 255) << 8) | ((q2 & 255) << 16) | ((q3 & 255) << 24);
        int sq = __reduce_add_sync(0xffffffffu, q0 + q1 + q2 + q3);
        sU   = wm * (1.0f / 127.0f);
        Bsum = sU * (float)sq;
    }
    __syncwarp();

    // 2-deep prefetch pipeline (em row as float4, mask broadcast)
    float4 ecur  = *(const float4*)&em[(1 * BB + b) * KK + j0];
    float  mcur  = __ldg(&mask[1 * BB + b]);
    float4 enext = *(const float4*)&em[(2 * BB + b) * KK + j0];
    float  mnext = __ldg(&mask[2 * BB + b]);

    for (int t = 1; t < TT; t++) {
        const int r = t & 1, w = r ^ 1;

        // exp(em) and its warp max early — redux latency hides under the matvec
        const float ex0 = __expf(ecur.x), ex1 = __expf(ecur.y);
        const float ex2 = __expf(ecur.z), ex3 = __expf(ecur.w);
        float exm = fmaxf(fmaxf(ex0, ex1), fmaxf(ex2, ex3));
        exm = __uint_as_float(__reduce_max_sync(0xffffffffu, __float_as_uint(exm)));

        // prefetch t+2 (clamped)
        const int tp = (t + 2 < TT) ? (t + 2) : (TT - 1);
        const float4 epre = *(const float4*)&em[(tp * BB + b) * KK + j0];
        const float  mpre = __ldg(&mask[tp * BB + b]);

        // int8 residual matvec: 4 chains (one per owned column)
        const uint4* qp = (const uint4*)&squ[wid][r][0];
        int a0 = 0, a1 = 0, a2 = 0, a3 = 0;
#pragma unroll
        for (int q = 0; q < 8; q++) {
            const uint4 Q = qp[q];
            a0 = __dp4a(rq[0][4*q+0], (int)Q.x, a0);
            a0 = __dp4a(rq[0][4*q+1], (int)Q.y, a0);
            a0 = __dp4a(rq[0][4*q+2], (int)Q.z, a0);
            a0 = __dp4a(rq[0][4*q+3], (int)Q.w, a0);
            a1 = __dp4a(rq[1][4*q+0], (int)Q.x, a1);
            a1 = __dp4a(rq[1][4*q+1], (int)Q.y, a1);
            a1 = __dp4a(rq[1][4*q+2], (int)Q.z, a1);
            a1 = __dp4a(rq[1][4*q+3], (int)Q.w, a1);
            a2 = __dp4a(rq[2][4*q+0], (int)Q.x, a2);
            a2 = __dp4a(rq[2][4*q+1], (int)Q.y, a2);
            a2 = __dp4a(rq[2][4*q+2], (int)Q.z, a2);
            a2 = __dp4a(rq[2][4*q+3], (int)Q.w, a2);
            a3 = __dp4a(rq[3][4*q+0], (int)Q.x, a3);
            a3 = __dp4a(rq[3][4*q+1], (int)Q.y, a3);
            a3 = __dp4a(rq[3][4*q+2], (int)Q.z, a3);
            a3 = __dp4a(rq[3][4*q+3], (int)Q.w, a3);
        }

        const float f  = sR * sU;
        const float S0 = fmaf(f, (float)a0, Bsum);
        const float S1 = fmaf(f, (float)a1, Bsum);
        const float S2 = fmaf(f, (float)a2, Bsum);
        const float S3 = fmaf(f, (float)a3, Bsum);
        const bool  mk = (mcur != 0.0f);
        u[0] = mk ? ex0 * S0 : u[0];
        u[1] = mk ? ex1 * S1 : u[1];
        u[2] = mk ? ex2 * S2 : u[2];
        u[3] = mk ? ex3 * S3 : u[3];

        // rotate prefetch pipeline
        ecur = enext;  mcur = mnext;
        enext = epre;  mnext = mpre;

        // rigorous scale bound (off critical path): max u <= max(exm*Bsum*(1+rmax), 127*sU)
        float bound = fmaxf(exm * Bsum * onePr, 127.0f * sU);

        // exact power-of-2 rescale every 8 steps (uses bound; any e keeps math exact)
        if ((t & 7) == 0) {
            const int   e = ilogbf(bound);
            const float s = __int_as_float((unsigned)(127 - e) << 23);  // exact 2^-e
            u[0] *= s; u[1] *= s; u[2] *= s; u[3] *= s;
            bound *= s;
            Ce += e;
        }

        // quantize + publish (scale from bound: no redux_max, no divide on the chain)
        const float inv = __fdividef(127.0f, bound);
        int q0 = min(__float2int_rn(u[0] * inv), 127);
        int q1 = min(__float2int_rn(u[1] * inv), 127);
        int q2 = min(__float2int_rn(u[2] * inv), 127);
        int q3 = min(__float2int_rn(u[3] * inv), 127);
        squ[wid][w][lane] = (q0 & 255) | ((q1 & 255) << 8) | ((q2 & 255) << 16) | ((q3 & 255) << 24);
        const int sq = __reduce_add_sync(0xffffffffu, q0 + q1 + q2 + q3);
        sU   = bound * (1.0f / 127.0f);
        Bsum = sU * (float)sq;
        __syncwarp();
    }

    // ---- finalize: -logZ = -(Ce*ln2 + log(sum_j u[j]*exp(end[j]))) ----
    float z;
    {
        const float4 ez = *(const float4*)&endT[j0];
        z = u[0] * __expf(ez.x) + u[1] * __expf(ez.y)
          + u[2] * __expf(ez.z) + u[3] * __expf(ez.w);
    }
    for (int o = 16; o; o >>= 1) z += __shfl_xor_sync(0xffffffffu, z, o);
    if (lane == 0) {
        double logZ = (double)Ce * 0.6931471805599453 + log((double)z);
        atomicAdd(out, g_path[b] + (float)(-logZ));
    }
}

extern "C" void kernel_launch(void* const* d_in, const int* in_sizes, int n_in,
                              void* d_out, int out_size) {
    const float* em     = (const float*)d_in[0];
    const int*   tags   = (const int*)  d_in[1];
    const float* mask   = (const float*)d_in[2];
    const float* startT = (const float*)d_in[3];
    const float* trans  = (const float*)d_in[4];
    const float* endT   = (const float*)d_in[5];
    float* out = (float*)d_out;

    path_kernel<<<BB, 128>>>(em, tags, mask, startT, trans, endT, out);
    crf_fwd_kernel<<<BB / 4, 128>>>(em, mask, startT, trans, endT, out);
}